// round 15
// baseline (speedup 1.0000x reference)
#include <cuda_runtime.h>
#include <cuda_fp16.h>
#include <cstdint>

// Problem constants
#define Bc    4
#define Tc    2048
#define DINc  2048
#define Hc    2048
#define Ec    8
#define RANKc 64
#define NANCH 512
#define SCALING 0.25f

// GEMM tiling
#define TM 128
#define TN 128
#define KC 64                          // fp32 K per chunk
#define NCHUNK (DINc / KC)             // 32
#define MTILES ((Bc * Tc) / TM)        // 64
#define NTILES (Hc / TN)               // 16
#define FRAGS_PER_CHUNK 1024           // (4 ksteps)*(8 blk16)*(32 lanes) uint4 frags
#define NITER (NCHUNK * 4)             // 128 ksteps total
#define KADV 256                       // frags per kstep

#define PACK_BLOCKS_A (MTILES * NCHUNK)   // 2048
#define PACK_BLOCKS_B (NTILES * NCHUNK)   // 512

__device__ int g_scale_i;
__device__ int g_counter;
// Fragment-ordered fp16 copies: A 32MB, B 8MB
__device__ __align__(16) uint4 g_fA[(size_t)MTILES * NCHUNK * FRAGS_PER_CHUNK];
__device__ __align__(16) uint4 g_fB[(size_t)NTILES * NCHUNK * FRAGS_PER_CHUNK];

// ---------------------------------------------------------------------------
// Helpers
// ---------------------------------------------------------------------------
__device__ __forceinline__ uint32_t pack_h2(float a, float b) {
    __half2 h = __floats2half2_rn(a, b);
    return *(uint32_t*)&h;
}
__device__ __forceinline__ void mma_fp16(float* c, const uint4& a, uint32_t b0, uint32_t b1) {
    asm volatile(
        "mma.sync.aligned.m16n8k16.row.col.f32.f16.f16.f32 "
        "{%0,%1,%2,%3},{%4,%5,%6,%7},{%8,%9},{%0,%1,%2,%3};"
        : "+f"(c[0]), "+f"(c[1]), "+f"(c[2]), "+f"(c[3])
        : "r"(a.x), "r"(a.y), "r"(a.z), "r"(a.w), "r"(b0), "r"(b1));
}

// ---------------------------------------------------------------------------
// Kernel P: smem-staged pack (MLP=8 batched loads). Also zeroes sync words.
// ---------------------------------------------------------------------------
__global__ __launch_bounds__(256) void pack_kernel(
    const float* __restrict__ xA, const float* __restrict__ wB)
{
    __shared__ uint32_t sh[128][32];

    if (blockIdx.x == 0 && threadIdx.x == 0) { g_scale_i = 0; g_counter = 0; }

    const bool isA  = blockIdx.x < PACK_BLOCKS_A;
    const int blkid = isA ? blockIdx.x : blockIdx.x - PACK_BLOCKS_A;
    const int tile  = blkid >> 5;
    const int chunk = blkid & 31;
    const int tid   = threadIdx.x;

    const float* base = (isA ? xA : wB) + ((size_t)tile * 128) * DINc + chunk * 64;
    const int row0 = tid >> 4;          // 0..15
    const int c4   = tid & 15;

    float4 v[8];
    #pragma unroll
    for (int p = 0; p < 8; p++) {
        int row = p * 16 + row0;
        v[p] = *(const float4*)(base + (size_t)row * DINc + c4 * 4);
    }
    #pragma unroll
    for (int p = 0; p < 8; p++) {
        int row = p * 16 + row0;
        uint32_t h0 = pack_h2(v[p].x, v[p].y);
        uint32_t h1 = pack_h2(v[p].z, v[p].w);
        int w0 = (c4 * 2 + (row & 7) * 4) & 31;
        *(uint2*)&sh[row][w0] = make_uint2(h0, h1);
    }
    __syncthreads();

    uint4* dst = (isA ? g_fA : g_fB) +
                 ((size_t)tile * NCHUNK + chunk) * FRAGS_PER_CHUNK;

    auto rd = [&](int rr, int ww) { return sh[rr][(ww + (rr & 7) * 4) & 31]; };

    #pragma unroll
    for (int p = 0; p < 4; p++) {
        int f    = p * 256 + tid;
        int lane = f & 31;
        int blk  = (f >> 5) & 7;
        int ks   = (f >> 8) & 3;
        int r = blk * 16 + (lane >> 2);
        int i = ks * 8 + (lane & 3);
        uint4 o;
        if (isA) {
            o.x = rd(r, i);     o.y = rd(r + 8, i);
            o.z = rd(r, i + 4); o.w = rd(r + 8, i + 4);
        } else {
            o.x = rd(r, i);     o.y = rd(r, i + 4);
            o.z = rd(r + 8, i); o.w = rd(r + 8, i + 4);
        }
        dst[f] = o;
    }
}

// ---------------------------------------------------------------------------
// Kernel 1: fp16 GEMM + FULLY FUSED epilogue (absmax / softmax / pmix / scale).
// 1D grid of 1024: bids 0..959 -> bx=1..15; bids 960..1023 -> bx=0 (LAST wave,
// so the 64 bx==0 CTAs are co-resident when they reach the spin barrier).
// ---------------------------------------------------------------------------
__global__ __launch_bounds__(256, 2) void gemm_fp16_kernel(
    const float* __restrict__ bias, const float* __restrict__ L,
    float* __restrict__ C)
{
    __shared__ float sLime[Ec * RANKc];   // [e][rank]
    __shared__ float sHs[32][Ec];         // anchor logit rows (cols 0..7)
    __shared__ float sw[32][Ec];          // normalized weights per anchor
    __shared__ float s_scale;

    const int tid    = threadIdx.x;
    const int lane   = tid & 31;
    const int wid    = tid >> 5;
    const int warp_m = wid >> 2;      // 0..1 -> rows *64
    const int warp_n = wid & 3;       // 0..3 -> cols *32

    int bid = blockIdx.x;
    int bx, by;
    if (bid < 960) { bx = 1 + (bid % 15); by = bid / 15; }
    else           { bx = 0;              by = bid - 960; }

    const uint4* pa = g_fA + (size_t)by * NCHUNK * FRAGS_PER_CHUNK
                          + warp_m * 128 + lane;
    const uint4* pb = g_fB + (size_t)bx * NCHUNK * FRAGS_PER_CHUNK
                          + warp_n * 64 + lane;

    float acc[4][4][4];
    #pragma unroll
    for (int i = 0; i < 4; i++)
        #pragma unroll
        for (int j = 0; j < 4; j++)
            #pragma unroll
            for (int k = 0; k < 4; k++) acc[i][j][k] = 0.0f;

    uint4 va[2][4], vb[2][2];

    #pragma unroll
    for (int j = 0; j < 2; j++)    vb[0][j]  = __ldg(pb + j * 32);
    #pragma unroll
    for (int mt = 0; mt < 4; mt++) va[0][mt] = __ldg(pa + mt * 32);
    pa += KADV; pb += KADV;

    #pragma unroll 1
    for (int it = 0; it < (NITER - 2) / 2; it++) {
        #pragma unroll
        for (int j = 0; j < 2; j++)    vb[1][j]  = __ldg(pb + j * 32);
        #pragma unroll
        for (int mt = 0; mt < 4; mt++) va[1][mt] = __ldg(pa + mt * 32);
        pa += KADV; pb += KADV;
        #pragma unroll
        for (int mt = 0; mt < 4; mt++)
            #pragma unroll
            for (int j = 0; j < 2; j++) {
                mma_fp16(acc[mt][2 * j],     va[0][mt], vb[0][j].x, vb[0][j].y);
                mma_fp16(acc[mt][2 * j + 1], va[0][mt], vb[0][j].z, vb[0][j].w);
            }
        #pragma unroll
        for (int j = 0; j < 2; j++)    vb[0][j]  = __ldg(pb + j * 32);
        #pragma unroll
        for (int mt = 0; mt < 4; mt++) va[0][mt] = __ldg(pa + mt * 32);
        pa += KADV; pb += KADV;
        #pragma unroll
        for (int mt = 0; mt < 4; mt++)
            #pragma unroll
            for (int j = 0; j < 2; j++) {
                mma_fp16(acc[mt][2 * j],     va[1][mt], vb[1][j].x, vb[1][j].y);
                mma_fp16(acc[mt][2 * j + 1], va[1][mt], vb[1][j].z, vb[1][j].w);
            }
    }

    #pragma unroll
    for (int j = 0; j < 2; j++)    vb[1][j]  = __ldg(pb + j * 32);
    #pragma unroll
    for (int mt = 0; mt < 4; mt++) va[1][mt] = __ldg(pa + mt * 32);
    #pragma unroll
    for (int mt = 0; mt < 4; mt++)
        #pragma unroll
        for (int j = 0; j < 2; j++) {
            mma_fp16(acc[mt][2 * j],     va[0][mt], vb[0][j].x, vb[0][j].y);
            mma_fp16(acc[mt][2 * j + 1], va[0][mt], vb[0][j].z, vb[0][j].w);
        }
    #pragma unroll
    for (int mt = 0; mt < 4; mt++)
        #pragma unroll
        for (int j = 0; j < 2; j++) {
            mma_fp16(acc[mt][2 * j],     va[1][mt], vb[1][j].x, vb[1][j].y);
            mma_fp16(acc[mt][2 * j + 1], va[1][mt], vb[1][j].z, vb[1][j].w);
        }

    const int row0 = by * TM + warp_m * 64;
    const int col0 = bx * TN + warp_n * 32;

    if (bx != 0) {
        // ---- plain epilogue ----
        #pragma unroll
        for (int mt = 0; mt < 4; mt++) {
            int r = row0 + mt * 16 + (lane >> 2);
            #pragma unroll
            for (int nt = 0; nt < 4; nt++) {
                int cc = col0 + nt * 8 + (lane & 3) * 2;
                float b0 = bias[cc], b1 = bias[cc + 1];
                const float* a = acc[mt][nt];
                *(float2*)(C + (size_t)r * Hc + cc) =
                    make_float2(a[0] + b0, a[1] + b1);
                *(float2*)(C + (size_t)(r + 8) * Hc + cc) =
                    make_float2(a[2] + b0, a[3] + b1);
            }
        }
        return;
    }

    // ---- bx == 0: fused anchor absmax + softmax + pmix + scaled store ----
    for (int i = tid; i < Ec * RANKc; i += 256) sLime[i] = L[i];

    if (warp_n >= 2) {
        // cols 64..127: never scaled, store immediately
        #pragma unroll
        for (int mt = 0; mt < 4; mt++) {
            int r = row0 + mt * 16 + (lane >> 2);
            #pragma unroll
            for (int nt = 0; nt < 4; nt++) {
                int cc = col0 + nt * 8 + (lane & 3) * 2;
                float b0 = bias[cc], b1 = bias[cc + 1];
                const float* a = acc[mt][nt];
                *(float2*)(C + (size_t)r * Hc + cc) =
                    make_float2(a[0] + b0, a[1] + b1);
                *(float2*)(C + (size_t)(r + 8) * Hc + cc) =
                    make_float2(a[2] + b0, a[3] + b1);
            }
        }
    } else if (warp_n == 0) {
        // anchor rows (local row % 4 == 3) in cols 0..7 -> sHs + local absmax
        float amax = 0.0f;
        int rsub = lane >> 2;                 // 0..7
        if ((rsub & 3) == 3) {
            #pragma unroll
            for (int mt = 0; mt < 4; mt++) {
                int cc = (lane & 3) * 2;
                float b0 = bias[cc], b1 = bias[cc + 1];
                const float* a = acc[mt][0];
                float h00 = a[0] + b0, h01 = a[1] + b1;   // row r
                float h10 = a[2] + b0, h11 = a[3] + b1;   // row r+8
                int la = warp_m * 16 + mt * 4 + (rsub >> 2);   // 0 or 1
                sHs[la][cc]     = h00; sHs[la][cc + 1]     = h01;
                sHs[la + 2][cc] = h10; sHs[la + 2][cc + 1] = h11;
                amax = fmaxf(amax, fmaxf(fabsf(h00), fabsf(h01)));
                amax = fmaxf(amax, fmaxf(fabsf(h10), fabsf(h11)));
            }
            atomicMax(&g_scale_i, __float_as_int(amax));
            __threadfence();
        }
    }
    __syncthreads();

    if (tid == 0) {
        atomicAdd(&g_counter, 1);
        while (atomicAdd(&g_counter, 0) < MTILES) { }
        s_scale = fmaxf(__int_as_float(atomicAdd(&g_scale_i, 0)), 1e-6f);
    }
    __syncthreads();

    if (tid < 32) {
        const float inv_scale = 1.0f / s_scale;
        float l[Ec], lmax = -1e30f;
        #pragma unroll
        for (int e = 0; e < Ec; e++) {
            l[e] = sHs[tid][e] * inv_scale;
            lmax = fmaxf(lmax, l[e]);
        }
        float p[Ec], s = 0.0f;
        #pragma unroll
        for (int e = 0; e < Ec; e++) { p[e] = expf(l[e] - lmax); s += p[e]; }
        float invs = 1.0f / s;
        #pragma unroll
        for (int e = 0; e < Ec; e++) p[e] *= invs;
        float m1 = -1e30f, m2 = -1e30f;
        #pragma unroll
        for (int e = 0; e < Ec; e++) {
            float v = p[e];
            if (v > m1) { m2 = m1; m1 = v; }
            else if (v > m2) { m2 = v; }
        }
        float w[Ec], ws = 0.0f;
        #pragma unroll
        for (int e = 0; e < Ec; e++) {
            float mask = 1.0f / (1.0f + expf(-(p[e] - m2) * 2.0f));
            w[e] = p[e] * mask;
            ws  += w[e];
        }
        float invws = 1.0f / (ws + 1e-9f);
        #pragma unroll
        for (int e = 0; e < Ec; e++) sw[tid][e] = w[e] * invws;
    }
    __syncthreads();

    if (warp_n < 2) {
        // cols 0..63: scale by (1 + SCALING * pmix) then store
        #pragma unroll
        for (int mt = 0; mt < 4; mt++) {
            int rl = warp_m * 64 + mt * 16 + (lane >> 2);   // local row
            int la0 = rl >> 2;                               // anchor of row rl
            int la1 = (rl + 8) >> 2;                         // = la0 + 2
            int r = by * TM + rl;
            #pragma unroll
            for (int nt = 0; nt < 4; nt++) {
                int cc = col0 + nt * 8 + (lane & 3) * 2;     // < 64
                float b0 = bias[cc], b1 = bias[cc + 1];
                const float* a = acc[mt][nt];
                float pm00 = 0.0f, pm01 = 0.0f, pm10 = 0.0f, pm11 = 0.0f;
                #pragma unroll
                for (int e = 0; e < Ec; e++) {
                    float l0 = sLime[e * RANKc + cc];
                    float l1 = sLime[e * RANKc + cc + 1];
                    pm00 += sw[la0][e] * l0;
                    pm01 += sw[la0][e] * l1;
                    pm10 += sw[la1][e] * l0;
                    pm11 += sw[la1][e] * l1;
                }
                float2 o0, o1;
                o0.x = (a[0] + b0) * (1.0f + SCALING * pm00);
                o0.y = (a[1] + b1) * (1.0f + SCALING * pm01);
                o1.x = (a[2] + b0) * (1.0f + SCALING * pm10);
                o1.y = (a[3] + b1) * (1.0f + SCALING * pm11);
                *(float2*)(C + (size_t)r * Hc + cc)       = o0;
                *(float2*)(C + (size_t)(r + 8) * Hc + cc) = o1;
            }
        }
    }
}

// ---------------------------------------------------------------------------
extern "C" void kernel_launch(void* const* d_in, const int* in_sizes, int n_in,
                              void* d_out, int out_size)
{
    const float* x = (const float*)d_in[0];   // [B*T, DIN]
    const float* W = (const float*)d_in[1];   // [H, DIN]
    const float* b = (const float*)d_in[2];   // [H]
    const float* L = (const float*)d_in[3];   // [E, RANK]
    float* out = (float*)d_out;

    pack_kernel<<<PACK_BLOCKS_A + PACK_BLOCKS_B, 256>>>(x, W);
    gemm_fp16_kernel<<<NTILES * MTILES, 256>>>(b, L, out);
}

// round 16
// speedup vs baseline: 1.0305x; 1.0305x over previous
#include <cuda_runtime.h>
#include <cuda_fp16.h>
#include <cstdint>

// Problem constants
#define Bc    4
#define Tc    2048
#define DINc  2048
#define Hc    2048
#define Ec    8
#define RANKc 64
#define NANCH 512
#define SCALING 0.25f

// GEMM tiling
#define TM 128
#define TN 128
#define KC 64                          // fp32 K per chunk
#define NCHUNK (DINc / KC)             // 32
#define MTILES ((Bc * Tc) / TM)        // 64
#define NTILES (Hc / TN)               // 16
#define FRAGS_PER_CHUNK 1024           // (4 ksteps)*(8 blk16)*(32 lanes) uint4 frags
#define NITER (NCHUNK * 4)             // 128 ksteps total
#define KADV 256                       // frags per kstep

#define PACK_BLOCKS_A (MTILES * NCHUNK)   // 2048
#define PACK_BLOCKS_B (NTILES * NCHUNK)   // 512

__device__ int g_scale_i;
// Fragment-ordered fp16 copies: A 32MB, B 8MB
__device__ __align__(16) uint4 g_fA[(size_t)MTILES * NCHUNK * FRAGS_PER_CHUNK];
__device__ __align__(16) uint4 g_fB[(size_t)NTILES * NCHUNK * FRAGS_PER_CHUNK];

// ---------------------------------------------------------------------------
// Helpers
// ---------------------------------------------------------------------------
__device__ __forceinline__ uint32_t pack_h2(float a, float b) {
    __half2 h = __floats2half2_rn(a, b);
    return *(uint32_t*)&h;
}
__device__ __forceinline__ void mma_fp16(float* c, const uint4& a, uint32_t b0, uint32_t b1) {
    asm volatile(
        "mma.sync.aligned.m16n8k16.row.col.f32.f16.f16.f32 "
        "{%0,%1,%2,%3},{%4,%5,%6,%7},{%8,%9},{%0,%1,%2,%3};"
        : "+f"(c[0]), "+f"(c[1]), "+f"(c[2]), "+f"(c[3])
        : "r"(a.x), "r"(a.y), "r"(a.z), "r"(a.w), "r"(b0), "r"(b1));
}

// ---------------------------------------------------------------------------
// Kernel P: smem-staged pack (bandwidth-bound).
// ---------------------------------------------------------------------------
__global__ __launch_bounds__(256) void pack_kernel(
    const float* __restrict__ xA, const float* __restrict__ wB)
{
    __shared__ uint32_t sh[128][32];

    if (blockIdx.x == 0 && threadIdx.x == 0) g_scale_i = 0;

    const bool isA  = blockIdx.x < PACK_BLOCKS_A;
    const int blkid = isA ? blockIdx.x : blockIdx.x - PACK_BLOCKS_A;
    const int tile  = blkid >> 5;
    const int chunk = blkid & 31;
    const int tid   = threadIdx.x;

    const float* base = (isA ? xA : wB) + ((size_t)tile * 128) * DINc + chunk * 64;

    #pragma unroll
    for (int p = 0; p < 8; p++) {
        int fi  = p * 256 + tid;        // 0..2047 float4s
        int row = fi >> 4;
        int c4  = fi & 15;
        float4 v = *(const float4*)(base + (size_t)row * DINc + c4 * 4);
        uint32_t h0 = pack_h2(v.x, v.y);
        uint32_t h1 = pack_h2(v.z, v.w);
        int w0 = (c4 * 2 + (row & 7) * 4) & 31;   // even, +1 stays in range
        *(uint2*)&sh[row][w0] = make_uint2(h0, h1);
    }
    __syncthreads();

    uint4* dst = (isA ? g_fA : g_fB) +
                 ((size_t)tile * NCHUNK + chunk) * FRAGS_PER_CHUNK;

    auto rd = [&](int rr, int ww) { return sh[rr][(ww + (rr & 7) * 4) & 31]; };

    #pragma unroll
    for (int p = 0; p < 4; p++) {
        int f    = p * 256 + tid;       // 0..1023 fragments
        int lane = f & 31;
        int blk  = (f >> 5) & 7;
        int ks   = (f >> 8) & 3;
        int r = blk * 16 + (lane >> 2);
        int i = ks * 8 + (lane & 3);
        uint4 v;
        if (isA) {
            v.x = rd(r, i);     v.y = rd(r + 8, i);
            v.z = rd(r, i + 4); v.w = rd(r + 8, i + 4);
        } else {
            v.x = rd(r, i);     v.y = rd(r, i + 4);
            v.z = rd(r + 8, i); v.w = rd(r + 8, i + 4);
        }
        dst[f] = v;
    }
}

// ---------------------------------------------------------------------------
// Kernel 1: fp16 m16n8k16 GEMM, SMEM-free, register double-buffered.
// 128x128 tile, 8 warps (2x4, each 64x32), 2 CTAs/SM, peeled mainloop.
// (R11 configuration — measured session best.)
// ---------------------------------------------------------------------------
__global__ __launch_bounds__(256, 2) void gemm_fp16_kernel(
    const float* __restrict__ bias, float* __restrict__ C)
{
    const int tid    = threadIdx.x;
    const int lane   = tid & 31;
    const int wid    = tid >> 5;
    const int warp_m = wid >> 2;      // 0..1 -> rows *64
    const int warp_n = wid & 3;       // 0..3 -> cols *32
    const int bx = blockIdx.x, by = blockIdx.y;

    // Per-lane fragment streams; advance KADV frags (4KB) per kstep.
    const uint4* pa = g_fA + (size_t)by * NCHUNK * FRAGS_PER_CHUNK
                          + warp_m * 128 + lane;
    const uint4* pb = g_fB + (size_t)bx * NCHUNK * FRAGS_PER_CHUNK
                          + warp_n * 64 + lane;

    float acc[4][4][4];
    #pragma unroll
    for (int i = 0; i < 4; i++)
        #pragma unroll
        for (int j = 0; j < 4; j++)
            #pragma unroll
            for (int k = 0; k < 4; k++) acc[i][j][k] = 0.0f;

    uint4 va[2][4], vb[2][2];

    // Prologue: load kstep 0 into buffer 0.
    #pragma unroll
    for (int j = 0; j < 2; j++)    vb[0][j]  = __ldg(pb + j * 32);
    #pragma unroll
    for (int mt = 0; mt < 4; mt++) va[0][mt] = __ldg(pa + mt * 32);
    pa += KADV; pb += KADV;

    // Main loop: 63 double-iterations (ksteps 0..125, prefetch 1..126).
    #pragma unroll 1
    for (int it = 0; it < (NITER - 2) / 2; it++) {
        #pragma unroll
        for (int j = 0; j < 2; j++)    vb[1][j]  = __ldg(pb + j * 32);
        #pragma unroll
        for (int mt = 0; mt < 4; mt++) va[1][mt] = __ldg(pa + mt * 32);
        pa += KADV; pb += KADV;
        #pragma unroll
        for (int mt = 0; mt < 4; mt++)
            #pragma unroll
            for (int j = 0; j < 2; j++) {
                mma_fp16(acc[mt][2 * j],     va[0][mt], vb[0][j].x, vb[0][j].y);
                mma_fp16(acc[mt][2 * j + 1], va[0][mt], vb[0][j].z, vb[0][j].w);
            }
        #pragma unroll
        for (int j = 0; j < 2; j++)    vb[0][j]  = __ldg(pb + j * 32);
        #pragma unroll
        for (int mt = 0; mt < 4; mt++) va[0][mt] = __ldg(pa + mt * 32);
        pa += KADV; pb += KADV;
        #pragma unroll
        for (int mt = 0; mt < 4; mt++)
            #pragma unroll
            for (int j = 0; j < 2; j++) {
                mma_fp16(acc[mt][2 * j],     va[1][mt], vb[1][j].x, vb[1][j].y);
                mma_fp16(acc[mt][2 * j + 1], va[1][mt], vb[1][j].z, vb[1][j].w);
            }
    }

    // Tail ksteps 126 (prefetch 127) and 127.
    #pragma unroll
    for (int j = 0; j < 2; j++)    vb[1][j]  = __ldg(pb + j * 32);
    #pragma unroll
    for (int mt = 0; mt < 4; mt++) va[1][mt] = __ldg(pa + mt * 32);
    #pragma unroll
    for (int mt = 0; mt < 4; mt++)
        #pragma unroll
        for (int j = 0; j < 2; j++) {
            mma_fp16(acc[mt][2 * j],     va[0][mt], vb[0][j].x, vb[0][j].y);
            mma_fp16(acc[mt][2 * j + 1], va[0][mt], vb[0][j].z, vb[0][j].w);
        }
    #pragma unroll
    for (int mt = 0; mt < 4; mt++)
        #pragma unroll
        for (int j = 0; j < 2; j++) {
            mma_fp16(acc[mt][2 * j],     va[1][mt], vb[1][j].x, vb[1][j].y);
            mma_fp16(acc[mt][2 * j + 1], va[1][mt], vb[1][j].z, vb[1][j].w);
        }

    // Epilogue + fused anchor absmax
    const int row0 = by * TM + warp_m * 64;
    const int col0 = bx * TN + warp_n * 32;
    float amax = 0.0f;
    const bool scale_zone = (bx == 0) && (warp_n == 0);   // cols 0..7 live in nt==0
    #pragma unroll
    for (int mt = 0; mt < 4; mt++) {
        int r = row0 + mt * 16 + (lane >> 2);
        #pragma unroll
        for (int nt = 0; nt < 4; nt++) {
            int cc = col0 + nt * 8 + (lane & 3) * 2;
            float b0 = bias[cc], b1 = bias[cc + 1];
            const float* a = acc[mt][nt];
            float2 o0 = make_float2(a[0] + b0, a[1] + b1);
            float2 o1 = make_float2(a[2] + b0, a[3] + b1);
            *(float2*)(C + (size_t)r * Hc + cc)       = o0;
            *(float2*)(C + (size_t)(r + 8) * Hc + cc) = o1;
            if (scale_zone && nt == 0) {
                if ((r & 3) == 3) {     // anchor rows: t % 4 == 3
                    amax = fmaxf(amax, fmaxf(fabsf(o0.x), fabsf(o0.y)));
                    amax = fmaxf(amax, fmaxf(fabsf(o1.x), fabsf(o1.y)));
                }
            }
        }
    }
    if (scale_zone && (lane & 12) == 12 && amax > 0.0f)
        atomicMax(&g_scale_i, __float_as_int(amax));
}

// ---------------------------------------------------------------------------
// Kernel 2: fused pmix + apply (R11 shape: 512 blocks, 4 anchors each).
// ---------------------------------------------------------------------------
__global__ __launch_bounds__(256) void apply_fused_kernel(
    float* __restrict__ C, const float* __restrict__ L)
{
    __shared__ float sL[Ec * RANKc];
    __shared__ float sw[4][Ec];

    const int tid = threadIdx.x;
    for (int i = tid; i < Ec * RANKc; i += 256) sL[i] = L[i];

    const int tg0 = blockIdx.x * 16;        // first (b*T+t) row
    const int b   = tg0 >> 11;
    const int a0  = (tg0 & (Tc - 1)) >> 2;  // first anchor of this block

    if (tid < 4) {
        const int t = (a0 + tid) * 4 + 3;
        const float* h = C + ((size_t)(b * Tc + t)) * Hc;
        const float inv_scale = 1.0f / fmaxf(__int_as_float(g_scale_i), 1e-6f);

        float l[Ec], lmax = -1e30f;
        #pragma unroll
        for (int e = 0; e < Ec; e++) {
            l[e] = h[e] * inv_scale;
            lmax = fmaxf(lmax, l[e]);
        }
        float p[Ec], s = 0.0f;
        #pragma unroll
        for (int e = 0; e < Ec; e++) { p[e] = expf(l[e] - lmax); s += p[e]; }
        float invs = 1.0f / s;
        #pragma unroll
        for (int e = 0; e < Ec; e++) p[e] *= invs;

        float m1 = -1e30f, m2 = -1e30f;
        #pragma unroll
        for (int e = 0; e < Ec; e++) {
            float v = p[e];
            if (v > m1) { m2 = m1; m1 = v; }
            else if (v > m2) { m2 = v; }
        }
        float w[Ec], ws = 0.0f;
        #pragma unroll
        for (int e = 0; e < Ec; e++) {
            float mask = 1.0f / (1.0f + expf(-(p[e] - m2) * 2.0f));
            w[e] = p[e] * mask;
            ws  += w[e];
        }
        float invws = 1.0f / (ws + 1e-9f);
        #pragma unroll
        for (int e = 0; e < Ec; e++) sw[tid][e] = w[e] * invws;
    }
    __syncthreads();

    const int r4  = tid & 15;          // float4 index within rank dim
    const int tgl = tid >> 4;          // 0..15 local row
    const int al  = tgl >> 2;          // 0..3 local anchor

    float pm[4];
    #pragma unroll
    for (int j = 0; j < 4; j++) {
        int r = r4 * 4 + j;
        float acc = 0.0f;
        #pragma unroll
        for (int e = 0; e < Ec; e++) acc += sw[al][e] * sL[e * RANKc + r];
        pm[j] = acc;
    }

    float4* cp = (float4*)(C + (size_t)(tg0 + tgl) * Hc) + r4;
    float4 v = *cp;
    v.x *= 1.0f + SCALING * pm[0];
    v.y *= 1.0f + SCALING * pm[1];
    v.z *= 1.0f + SCALING * pm[2];
    v.w *= 1.0f + SCALING * pm[3];
    *cp = v;
}

// ---------------------------------------------------------------------------
extern "C" void kernel_launch(void* const* d_in, const int* in_sizes, int n_in,
                              void* d_out, int out_size)
{
    const float* x = (const float*)d_in[0];   // [B*T, DIN]
    const float* W = (const float*)d_in[1];   // [H, DIN]
    const float* b = (const float*)d_in[2];   // [H]
    const float* L = (const float*)d_in[3];   // [E, RANK]
    float* out = (float*)d_out;

    pack_kernel<<<PACK_BLOCKS_A + PACK_BLOCKS_B, 256>>>(x, W);

    dim3 grid(NTILES, MTILES);   // (16, 64)
    gemm_fp16_kernel<<<grid, 256>>>(b, out);

    apply_fused_kernel<<<(Bc * Tc) / 16, 256>>>(out, L);
}

// round 17
// speedup vs baseline: 1.0546x; 1.0234x over previous
#include <cuda_runtime.h>
#include <cuda_fp16.h>
#include <cstdint>

// Problem constants
#define Bc    4
#define Tc    2048
#define DINc  2048
#define Hc    2048
#define Ec    8
#define RANKc 64
#define NANCH 512
#define SCALING 0.25f

// GEMM tiling
#define TM 128
#define TN 128
#define KC 64                          // fp32 K per chunk
#define NCHUNK (DINc / KC)             // 32
#define MTILES ((Bc * Tc) / TM)        // 64
#define NTILES (Hc / TN)               // 16
#define FRAGS_PER_CHUNK 1024           // (4 ksteps)*(8 blk16)*(32 lanes) uint4 frags
#define NITER (NCHUNK * 4)             // 128 ksteps total
#define KADV 256                       // frags per kstep

#define PACK_BLOCKS_A (MTILES * NCHUNK)   // 2048
#define PACK_BLOCKS_B (NTILES * NCHUNK)   // 512

__device__ int g_scale_i;
// Fragment-ordered fp16 copies: A 32MB, B 8MB
__device__ __align__(16) uint4 g_fA[(size_t)MTILES * NCHUNK * FRAGS_PER_CHUNK];
__device__ __align__(16) uint4 g_fB[(size_t)NTILES * NCHUNK * FRAGS_PER_CHUNK];

// ---------------------------------------------------------------------------
// Helpers
// ---------------------------------------------------------------------------
__device__ __forceinline__ uint32_t pack_h2(float a, float b) {
    __half2 h = __floats2half2_rn(a, b);
    return *(uint32_t*)&h;
}
__device__ __forceinline__ void mma_fp16(float* c, const uint4& a, uint32_t b0, uint32_t b1) {
    asm volatile(
        "mma.sync.aligned.m16n8k16.row.col.f32.f16.f16.f32 "
        "{%0,%1,%2,%3},{%4,%5,%6,%7},{%8,%9},{%0,%1,%2,%3};"
        : "+f"(c[0]), "+f"(c[1]), "+f"(c[2]), "+f"(c[3])
        : "r"(a.x), "r"(a.y), "r"(a.z), "r"(a.w), "r"(b0), "r"(b1));
}
#define GDC_WAIT()   asm volatile("griddepcontrol.wait;" ::: "memory")
#define GDC_LAUNCH() asm volatile("griddepcontrol.launch_dependents;" ::: "memory")

// ---------------------------------------------------------------------------
// Kernel P: smem-staged pack (bandwidth-bound, R11 form).
// ---------------------------------------------------------------------------
__global__ __launch_bounds__(256) void pack_kernel(
    const float* __restrict__ xA, const float* __restrict__ wB)
{
    __shared__ uint32_t sh[128][32];

    if (blockIdx.x == 0 && threadIdx.x == 0) g_scale_i = 0;

    const bool isA  = blockIdx.x < PACK_BLOCKS_A;
    const int blkid = isA ? blockIdx.x : blockIdx.x - PACK_BLOCKS_A;
    const int tile  = blkid >> 5;
    const int chunk = blkid & 31;
    const int tid   = threadIdx.x;

    const float* base = (isA ? xA : wB) + ((size_t)tile * 128) * DINc + chunk * 64;

    #pragma unroll
    for (int p = 0; p < 8; p++) {
        int fi  = p * 256 + tid;        // 0..2047 float4s
        int row = fi >> 4;
        int c4  = fi & 15;
        float4 v = *(const float4*)(base + (size_t)row * DINc + c4 * 4);
        uint32_t h0 = pack_h2(v.x, v.y);
        uint32_t h1 = pack_h2(v.z, v.w);
        int w0 = (c4 * 2 + (row & 7) * 4) & 31;   // even, +1 stays in range
        *(uint2*)&sh[row][w0] = make_uint2(h0, h1);
    }
    __syncthreads();

    uint4* dst = (isA ? g_fA : g_fB) +
                 ((size_t)tile * NCHUNK + chunk) * FRAGS_PER_CHUNK;

    auto rd = [&](int rr, int ww) { return sh[rr][(ww + (rr & 7) * 4) & 31]; };

    #pragma unroll
    for (int p = 0; p < 4; p++) {
        int f    = p * 256 + tid;       // 0..1023 fragments
        int lane = f & 31;
        int blk  = (f >> 5) & 7;
        int ks   = (f >> 8) & 3;
        int r = blk * 16 + (lane >> 2);
        int i = ks * 8 + (lane & 3);
        uint4 v;
        if (isA) {
            v.x = rd(r, i);     v.y = rd(r + 8, i);
            v.z = rd(r, i + 4); v.w = rd(r + 8, i + 4);
        } else {
            v.x = rd(r, i);     v.y = rd(r, i + 4);
            v.z = rd(r + 8, i); v.w = rd(r + 8, i + 4);
        }
        dst[f] = v;
    }
    GDC_LAUNCH();
}

// ---------------------------------------------------------------------------
// Kernel 1: fp16 m16n8k16 GEMM, SMEM-free, register double-buffered.
// 128x128 tile, 8 warps (2x4, each 64x32), 2 CTAs/SM, peeled mainloop.
// PDL: waits on pack before first fragment load; releases apply after mainloop.
// ---------------------------------------------------------------------------
__global__ __launch_bounds__(256, 2) void gemm_fp16_kernel(
    const float* __restrict__ bias, float* __restrict__ C)
{
    const int tid    = threadIdx.x;
    const int lane   = tid & 31;
    const int wid    = tid >> 5;
    const int warp_m = wid >> 2;      // 0..1 -> rows *64
    const int warp_n = wid & 3;       // 0..3 -> cols *32
    const int bx = blockIdx.x, by = blockIdx.y;

    // Per-lane fragment streams; advance KADV frags (4KB) per kstep.
    const uint4* pa = g_fA + (size_t)by * NCHUNK * FRAGS_PER_CHUNK
                          + warp_m * 128 + lane;
    const uint4* pb = g_fB + (size_t)bx * NCHUNK * FRAGS_PER_CHUNK
                          + warp_n * 64 + lane;

    float acc[4][4][4];
    #pragma unroll
    for (int i = 0; i < 4; i++)
        #pragma unroll
        for (int j = 0; j < 4; j++)
            #pragma unroll
            for (int k = 0; k < 4; k++) acc[i][j][k] = 0.0f;

    uint4 va[2][4], vb[2][2];

    GDC_WAIT();     // pack's fragment stores must be visible

    // Prologue: load kstep 0 into buffer 0.
    #pragma unroll
    for (int j = 0; j < 2; j++)    vb[0][j]  = __ldg(pb + j * 32);
    #pragma unroll
    for (int mt = 0; mt < 4; mt++) va[0][mt] = __ldg(pa + mt * 32);
    pa += KADV; pb += KADV;

    // Main loop: 63 double-iterations (ksteps 0..125, prefetch 1..126).
    #pragma unroll 1
    for (int it = 0; it < (NITER - 2) / 2; it++) {
        #pragma unroll
        for (int j = 0; j < 2; j++)    vb[1][j]  = __ldg(pb + j * 32);
        #pragma unroll
        for (int mt = 0; mt < 4; mt++) va[1][mt] = __ldg(pa + mt * 32);
        pa += KADV; pb += KADV;
        #pragma unroll
        for (int mt = 0; mt < 4; mt++)
            #pragma unroll
            for (int j = 0; j < 2; j++) {
                mma_fp16(acc[mt][2 * j],     va[0][mt], vb[0][j].x, vb[0][j].y);
                mma_fp16(acc[mt][2 * j + 1], va[0][mt], vb[0][j].z, vb[0][j].w);
            }
        #pragma unroll
        for (int j = 0; j < 2; j++)    vb[0][j]  = __ldg(pb + j * 32);
        #pragma unroll
        for (int mt = 0; mt < 4; mt++) va[0][mt] = __ldg(pa + mt * 32);
        pa += KADV; pb += KADV;
        #pragma unroll
        for (int mt = 0; mt < 4; mt++)
            #pragma unroll
            for (int j = 0; j < 2; j++) {
                mma_fp16(acc[mt][2 * j],     va[1][mt], vb[1][j].x, vb[1][j].y);
                mma_fp16(acc[mt][2 * j + 1], va[1][mt], vb[1][j].z, vb[1][j].w);
            }
    }

    // Tail ksteps 126 (prefetch 127) and 127.
    #pragma unroll
    for (int j = 0; j < 2; j++)    vb[1][j]  = __ldg(pb + j * 32);
    #pragma unroll
    for (int mt = 0; mt < 4; mt++) va[1][mt] = __ldg(pa + mt * 32);
    #pragma unroll
    for (int mt = 0; mt < 4; mt++)
        #pragma unroll
        for (int j = 0; j < 2; j++) {
            mma_fp16(acc[mt][2 * j],     va[0][mt], vb[0][j].x, vb[0][j].y);
            mma_fp16(acc[mt][2 * j + 1], va[0][mt], vb[0][j].z, vb[0][j].w);
        }
    #pragma unroll
    for (int mt = 0; mt < 4; mt++)
        #pragma unroll
        for (int j = 0; j < 2; j++) {
            mma_fp16(acc[mt][2 * j],     va[1][mt], vb[1][j].x, vb[1][j].y);
            mma_fp16(acc[mt][2 * j + 1], va[1][mt], vb[1][j].z, vb[1][j].w);
        }

    GDC_LAUNCH();   // let apply's grid spin up under our epilogue

    // Epilogue + fused anchor absmax
    const int row0 = by * TM + warp_m * 64;
    const int col0 = bx * TN + warp_n * 32;
    float amax = 0.0f;
    const bool scale_zone = (bx == 0) && (warp_n == 0);   // cols 0..7 live in nt==0
    #pragma unroll
    for (int mt = 0; mt < 4; mt++) {
        int r = row0 + mt * 16 + (lane >> 2);
        #pragma unroll
        for (int nt = 0; nt < 4; nt++) {
            int cc = col0 + nt * 8 + (lane & 3) * 2;
            float b0 = bias[cc], b1 = bias[cc + 1];
            const float* a = acc[mt][nt];
            float2 o0 = make_float2(a[0] + b0, a[1] + b1);
            float2 o1 = make_float2(a[2] + b0, a[3] + b1);
            *(float2*)(C + (size_t)r * Hc + cc)       = o0;
            *(float2*)(C + (size_t)(r + 8) * Hc + cc) = o1;
            if (scale_zone && nt == 0) {
                if ((r & 3) == 3) {     // anchor rows: t % 4 == 3
                    amax = fmaxf(amax, fmaxf(fabsf(o0.x), fabsf(o0.y)));
                    amax = fmaxf(amax, fmaxf(fabsf(o1.x), fabsf(o1.y)));
                }
            }
        }
    }
    if (scale_zone && (lane & 12) == 12 && amax > 0.0f)
        atomicMax(&g_scale_i, __float_as_int(amax));
}

// ---------------------------------------------------------------------------
// Kernel 2: fused pmix + apply (R11 shape: 512 blocks, 4 anchors each).
// PDL: loads LiMEs table BEFORE waiting on the GEMM.
// ---------------------------------------------------------------------------
__global__ __launch_bounds__(256) void apply_fused_kernel(
    float* __restrict__ C, const float* __restrict__ L)
{
    __shared__ float sL[Ec * RANKc];
    __shared__ float sw[4][Ec];

    const int tid = threadIdx.x;
    // Independent of GEMM output — do it before the dependency wait.
    for (int i = tid; i < Ec * RANKc; i += 256) sL[i] = L[i];

    GDC_WAIT();     // C and g_scale_i must be visible

    const int tg0 = blockIdx.x * 16;        // first (b*T+t) row
    const int b   = tg0 >> 11;
    const int a0  = (tg0 & (Tc - 1)) >> 2;  // first anchor of this block

    if (tid < 4) {
        const int t = (a0 + tid) * 4 + 3;
        const float* h = C + ((size_t)(b * Tc + t)) * Hc;
        const float inv_scale = 1.0f / fmaxf(__int_as_float(g_scale_i), 1e-6f);

        float l[Ec], lmax = -1e30f;
        #pragma unroll
        for (int e = 0; e < Ec; e++) {
            l[e] = h[e] * inv_scale;
            lmax = fmaxf(lmax, l[e]);
        }
        float p[Ec], s = 0.0f;
        #pragma unroll
        for (int e = 0; e < Ec; e++) { p[e] = expf(l[e] - lmax); s += p[e]; }
        float invs = 1.0f / s;
        #pragma unroll
        for (int e = 0; e < Ec; e++) p[e] *= invs;

        float m1 = -1e30f, m2 = -1e30f;
        #pragma unroll
        for (int e = 0; e < Ec; e++) {
            float v = p[e];
            if (v > m1) { m2 = m1; m1 = v; }
            else if (v > m2) { m2 = v; }
        }
        float w[Ec], ws = 0.0f;
        #pragma unroll
        for (int e = 0; e < Ec; e++) {
            float mask = 1.0f / (1.0f + expf(-(p[e] - m2) * 2.0f));
            w[e] = p[e] * mask;
            ws  += w[e];
        }
        float invws = 1.0f / (ws + 1e-9f);
        #pragma unroll
        for (int e = 0; e < Ec; e++) sw[tid][e] = w[e] * invws;
    }
    __syncthreads();

    const int r4  = tid & 15;          // float4 index within rank dim
    const int tgl = tid >> 4;          // 0..15 local row
    const int al  = tgl >> 2;          // 0..3 local anchor

    float pm[4];
    #pragma unroll
    for (int j = 0; j < 4; j++) {
        int r = r4 * 4 + j;
        float acc = 0.0f;
        #pragma unroll
        for (int e = 0; e < Ec; e++) acc += sw[al][e] * sL[e * RANKc + r];
        pm[j] = acc;
    }

    float4* cp = (float4*)(C + (size_t)(tg0 + tgl) * Hc) + r4;
    float4 v = *cp;
    v.x *= 1.0f + SCALING * pm[0];
    v.y *= 1.0f + SCALING * pm[1];
    v.z *= 1.0f + SCALING * pm[2];
    v.w *= 1.0f + SCALING * pm[3];
    *cp = v;
}

// ---------------------------------------------------------------------------
extern "C" void kernel_launch(void* const* d_in, const int* in_sizes, int n_in,
                              void* d_out, int out_size)
{
    const float* x = (const float*)d_in[0];   // [B*T, DIN]
    const float* W = (const float*)d_in[1];   // [H, DIN]
    const float* b = (const float*)d_in[2];   // [H]
    const float* L = (const float*)d_in[3];   // [E, RANK]
    float* out = (float*)d_out;

    // 1) pack (plain launch)
    pack_kernel<<<PACK_BLOCKS_A + PACK_BLOCKS_B, 256>>>(x, W);

    // 2) GEMM with PDL dependency on pack
    {
        cudaLaunchAttribute attr[1];
        attr[0].id = cudaLaunchAttributeProgrammaticStreamSerialization;
        attr[0].val.programmaticStreamSerializationAllowed = 1;
        cudaLaunchConfig_t cfg = {};
        cfg.gridDim  = dim3(NTILES, MTILES, 1);   // (16, 64)
        cfg.blockDim = dim3(256, 1, 1);
        cfg.attrs    = attr;
        cfg.numAttrs = 1;
        cudaLaunchKernelEx(&cfg, gemm_fp16_kernel, b, out);
    }

    // 3) apply with PDL dependency on GEMM
    {
        cudaLaunchAttribute attr[1];
        attr[0].id = cudaLaunchAttributeProgrammaticStreamSerialization;
        attr[0].val.programmaticStreamSerializationAllowed = 1;
        cudaLaunchConfig_t cfg = {};
        cfg.gridDim  = dim3((Bc * Tc) / 16, 1, 1);
        cfg.blockDim = dim3(256, 1, 1);
        cfg.attrs    = attr;
        cfg.numAttrs = 1;
        cudaLaunchKernelEx(&cfg, apply_fused_kernel, out, L);
    }
}